// round 4
// baseline (speedup 1.0000x reference)
#include <cuda_runtime.h>
#include <cstdint>

// Problem dims
#define T_STEPS 256
#define BATCH   128
#define INDIM   1024
#define HID     1024
#define OUTDIM  256
#define MROWS   (T_STEPS * BATCH)   // 32768
#define BETA_F  0.9f

// Eigen gebp panel depth hypothesis (two panels of 512 over K=1024)
#define KC      512

// Scratch (allocation-free rule: __device__ globals)
__device__ float g_cur1[(size_t)MROWS * HID];    // 128 MB
__device__ float g_cur2[(size_t)MROWS * OUTDIM]; // 32 MB

// ---------------------------------------------------------------------------
// SGEMM NT: C[M,N] = A[M,K] * B[N,K]^T + bias[N]
// Numerics contract (bit-match Eigen gebp with kc=512):
//   per output element: S = fadd( chain(k=0..511), chain(k=512..1023) )
//   where each chain is a sequential ascending-k FFMA chain from 0.0f.
//   Then ONE separately-rounded bias add.
// Tile 128x64x16, 256 threads, 8(m) x 4(n) microtile per thread.
// ---------------------------------------------------------------------------
#define BM 128
#define BN 64
#define BK 16

__global__ __launch_bounds__(256, 2)
void sgemm_nt(const float* __restrict__ A,
              const float* __restrict__ B,
              const float* __restrict__ bias,
              float* __restrict__ C,
              int M, int N, int K)
{
    __shared__ float As[BK][BM];
    __shared__ float Bs[BK][BN];

    const int tid = threadIdx.x;
    const int bm = blockIdx.y * BM;
    const int bn = blockIdx.x * BN;

    // global-load indexing
    const int lr = tid >> 2;          // 0..63
    const int lc = (tid & 3) << 2;    // 0,4,8,12

    // compute indexing: 16 thread-cols x 16 thread-rows
    const int tx = (tid & 15) << 2;   // 0..60  (n base, 4 wide)
    const int ty = (tid >> 4) << 3;   // 0..120 (m base, 8 tall)

    float sum[8][4];   // cross-panel accumulator (folded once per KC panel)
    float acc[8][4];   // within-panel ascending FFMA chain
    #pragma unroll
    for (int i = 0; i < 8; i++)
        #pragma unroll
        for (int j = 0; j < 4; j++) { sum[i][j] = 0.f; acc[i][j] = 0.f; }

    for (int k0 = 0; k0 < K; k0 += BK) {
        // load A tile (BMxBK), store transposed As[k][m]
        #pragma unroll
        for (int r = 0; r < BM; r += 64) {
            float4 v = *reinterpret_cast<const float4*>(
                &A[(size_t)(bm + lr + r) * K + (k0 + lc)]);
            As[lc + 0][lr + r] = v.x;
            As[lc + 1][lr + r] = v.y;
            As[lc + 2][lr + r] = v.z;
            As[lc + 3][lr + r] = v.w;
        }
        // load B tile (BNxBK), store transposed Bs[k][n]
        {
            float4 v = *reinterpret_cast<const float4*>(
                &B[(size_t)(bn + lr) * K + (k0 + lc)]);
            Bs[lc + 0][lr] = v.x;
            Bs[lc + 1][lr] = v.y;
            Bs[lc + 2][lr] = v.z;
            Bs[lc + 3][lr] = v.w;
        }
        __syncthreads();

        // ascending-k FFMA chain within the current KC panel
        #pragma unroll
        for (int k = 0; k < BK; k++) {
            float4 a0 = *reinterpret_cast<const float4*>(&As[k][ty]);
            float4 a1 = *reinterpret_cast<const float4*>(&As[k][ty + 4]);
            float4 b0 = *reinterpret_cast<const float4*>(&Bs[k][tx]);
            float a[8] = {a0.x, a0.y, a0.z, a0.w, a1.x, a1.y, a1.z, a1.w};
            float b[4] = {b0.x, b0.y, b0.z, b0.w};
            #pragma unroll
            for (int i = 0; i < 8; i++)
                #pragma unroll
                for (int j = 0; j < 4; j++)
                    acc[i][j] = __fmaf_rn(a[i], b[j], acc[i][j]);
        }

        // panel boundary: fold chain into cross-panel sum with ONE rounded add
        if ((k0 + BK) % KC == 0) {
            #pragma unroll
            for (int i = 0; i < 8; i++)
                #pragma unroll
                for (int j = 0; j < 4; j++) {
                    sum[i][j] = __fadd_rn(sum[i][j], acc[i][j]);
                    acc[i][j] = 0.f;
                }
        }

        __syncthreads();
    }

    // epilogue: ONE separately-rounded bias add, then store
    #pragma unroll
    for (int i = 0; i < 8; i++) {
        int row = bm + ty + i;
        int col = bn + tx;
        float4 v;
        v.x = __fadd_rn(sum[i][0], bias[col + 0]);
        v.y = __fadd_rn(sum[i][1], bias[col + 1]);
        v.z = __fadd_rn(sum[i][2], bias[col + 2]);
        v.w = __fadd_rn(sum[i][3], bias[col + 3]);
        *reinterpret_cast<float4*>(&C[(size_t)row * N + col]) = v;
    }
}

// ---------------------------------------------------------------------------
// LIF recurrence with XLA-exact op ordering (NO FMA contraction — each HLO op
// separately rounded, Python evaluation order):
//   t0 = BETA*mem ; t1 = t0 + cur ; t2 = spk*thr ; mem = t1 - t2
//   spk = (mem - thr > 0) ? 1 : 0
// Each thread owns one (b, n) neuron, loops over T steps. Coalesced.
// ---------------------------------------------------------------------------
__global__ void lif_scan(const float* __restrict__ cur,
                         const float* __restrict__ thr_p,
                         float* __restrict__ spk_rec,
                         int stride /* BATCH*N per timestep */)
{
    const int idx = blockIdx.x * blockDim.x + threadIdx.x;
    const float thr = *thr_p;
    float mem = 0.f;
    float s = 0.f;
    const float* p = cur + idx;
    float* q = spk_rec + idx;
    #pragma unroll 8
    for (int t = 0; t < T_STEPS; t++) {
        float c = p[(size_t)t * stride];
        float t0 = __fmul_rn(BETA_F, mem);
        float t1 = __fadd_rn(t0, c);
        float t2 = __fmul_rn(s, thr);
        mem = __fsub_rn(t1, t2);
        s = (__fsub_rn(mem, thr) > 0.f) ? 1.0f : 0.0f;
        q[(size_t)t * stride] = s;
    }
}

// ---------------------------------------------------------------------------
extern "C" void kernel_launch(void* const* d_in, const int* in_sizes, int n_in,
                              void* d_out, int out_size)
{
    const float* x    = (const float*)d_in[0];  // [T,B,I]
    const float* w1   = (const float*)d_in[1];  // [H,I]
    const float* b1   = (const float*)d_in[2];  // [H]
    const float* w2   = (const float*)d_in[3];  // [O,H]
    const float* b2   = (const float*)d_in[4];  // [O]
    const float* thr1 = (const float*)d_in[5];  // scalar
    const float* thr2 = (const float*)d_in[6];  // scalar

    float* out  = (float*)d_out;
    float* spk1 = out;                                    // [T,B,H]
    float* spk2 = out + (size_t)T_STEPS * BATCH * HID;    // [T,B,O]

    float* cur1 = nullptr;
    float* cur2 = nullptr;
    cudaGetSymbolAddress((void**)&cur1, g_cur1);
    cudaGetSymbolAddress((void**)&cur2, g_cur2);

    // 1) cur1 = X @ W1^T + b1   (32768 x 1024, K=1024)
    {
        dim3 grid(HID / BN, MROWS / BM);
        sgemm_nt<<<grid, 256>>>(x, w1, b1, cur1, MROWS, HID, INDIM);
    }
    // 2) LIF layer 1 -> spk1_rec (direct to output)
    lif_scan<<<(BATCH * HID) / 256, 256>>>(cur1, thr1, spk1, BATCH * HID);

    // 3) cur2 = spk1_rec @ W2^T + b2   (32768 x 256, K=1024)
    {
        dim3 grid(OUTDIM / BN, MROWS / BM);
        sgemm_nt<<<grid, 256>>>(spk1, w2, b2, cur2, MROWS, OUTDIM, HID);
    }
    // 4) LIF layer 2 -> spk2_rec
    lif_scan<<<(BATCH * OUTDIM) / 256, 256>>>(cur2, thr2, spk2, BATCH * OUTDIM);
}

// round 5
// speedup vs baseline: 1.0257x; 1.0257x over previous
#include <cuda_runtime.h>
#include <cstdint>

// Problem dims
#define T_STEPS 256
#define BATCH   128
#define INDIM   1024
#define HID     1024
#define OUTDIM  256
#define MROWS   (T_STEPS * BATCH)   // 32768
#define BETA_F  0.9f
#define KC      512                 // Eigen gebp panel depth (bit-exactness contract)

// Scratch (allocation-free rule: __device__ globals)
__device__ float g_cur1[(size_t)MROWS * HID];    // 128 MB
__device__ float g_cur2[(size_t)MROWS * OUTDIM]; // 32 MB

typedef unsigned long long ull;

// ---- packed f32x2 helpers (each lane = independent IEEE fp32 rn op) --------
__device__ __forceinline__ void ffma2(ull& d, ull a, ull b) {
    asm("fma.rn.f32x2 %0, %1, %2, %0;" : "+l"(d) : "l"(a), "l"(b));
}
__device__ __forceinline__ void fadd2(ull& d, ull a) {
    asm("add.rn.f32x2 %0, %0, %1;" : "+l"(d) : "l"(a));
}
__device__ __forceinline__ ull bcast2(float x) {
    ull r; asm("mov.b64 %0, {%1, %1};" : "=l"(r) : "f"(x)); return r;
}

// ---------------------------------------------------------------------------
// SGEMM NT: C[M,N] = A[M,K] * B[N,K]^T + bias[N], using FFMA2 (fp32x2).
// Numerics contract (bit-match Eigen gebp kc=512, VERIFIED rel_err==0):
//   per element: S = fadd( chain(k=0..511), chain(k=512..1023) ), chains are
//   ascending-k fp32 FMA chains from 0; then ONE rounded bias add.
// Each f32x2 lane carries one output element -> per-lane order identical.
// Tile 128x128x16, 256 threads, microtile 8m x 8n (acc paired over n).
// Double-buffered smem, register-staged global prefetch, 1 sync/iter.
// ---------------------------------------------------------------------------
#define BM 128
#define BN 128
#define BK 16

__global__ __launch_bounds__(256, 1)
void sgemm_nt_x2(const float* __restrict__ A,
                 const float* __restrict__ B,
                 const float* __restrict__ bias,
                 float* __restrict__ C,
                 int M, int N, int K)
{
    __shared__ float As[2][BK][BM];
    __shared__ float Bs[2][BK][BN];

    const int tid = threadIdx.x;
    const int bm = blockIdx.y * BM;
    const int bn = blockIdx.x * BN;

    // global-load indexing: each thread stages 2 float4 from A and 2 from B
    const int lr = tid >> 2;          // 0..63
    const int lc = (tid & 3) << 2;    // 0,4,8,12

    // compute indexing: quadrant layout (16B-contiguous across 16 threads ->
    // conflict-free LDS.128)
    const int tx = (tid & 15) << 2;   // n base (4 wide) ; second group at +64
    const int ty = (tid >> 4) << 2;   // m base (4 tall) ; second group at +64

    ull acc[8][4];   // within-panel chains: 8 m x 4 n-pairs
    ull sum[8][4];   // cross-panel accumulator
    #pragma unroll
    for (int i = 0; i < 8; i++)
        #pragma unroll
        for (int j = 0; j < 4; j++) { acc[i][j] = 0ull; sum[i][j] = 0ull; }

    // ---- prologue: stage tile 0, commit to buffer 0 ----
    float4 stA0 = *reinterpret_cast<const float4*>(&A[(size_t)(bm + lr) * K + lc]);
    float4 stA1 = *reinterpret_cast<const float4*>(&A[(size_t)(bm + lr + 64) * K + lc]);
    float4 stB0 = *reinterpret_cast<const float4*>(&B[(size_t)(bn + lr) * K + lc]);
    float4 stB1 = *reinterpret_cast<const float4*>(&B[(size_t)(bn + lr + 64) * K + lc]);

    As[0][lc + 0][lr] = stA0.x; As[0][lc + 1][lr] = stA0.y;
    As[0][lc + 2][lr] = stA0.z; As[0][lc + 3][lr] = stA0.w;
    As[0][lc + 0][lr + 64] = stA1.x; As[0][lc + 1][lr + 64] = stA1.y;
    As[0][lc + 2][lr + 64] = stA1.z; As[0][lc + 3][lr + 64] = stA1.w;
    Bs[0][lc + 0][lr] = stB0.x; Bs[0][lc + 1][lr] = stB0.y;
    Bs[0][lc + 2][lr] = stB0.z; Bs[0][lc + 3][lr] = stB0.w;
    Bs[0][lc + 0][lr + 64] = stB1.x; Bs[0][lc + 1][lr + 64] = stB1.y;
    Bs[0][lc + 2][lr + 64] = stB1.z; Bs[0][lc + 3][lr + 64] = stB1.w;
    __syncthreads();

    const int NIT = K / BK;  // 64
    int buf = 0;

    for (int iter = 0; iter < NIT; iter++) {
        // prefetch next tile into registers (latency hidden by compute)
        if (iter + 1 < NIT) {
            const int kn = (iter + 1) * BK + lc;
            stA0 = *reinterpret_cast<const float4*>(&A[(size_t)(bm + lr) * K + kn]);
            stA1 = *reinterpret_cast<const float4*>(&A[(size_t)(bm + lr + 64) * K + kn]);
            stB0 = *reinterpret_cast<const float4*>(&B[(size_t)(bn + lr) * K + kn]);
            stB1 = *reinterpret_cast<const float4*>(&B[(size_t)(bn + lr + 64) * K + kn]);
        }

        // compute: ascending-k FFMA2 chains
        #pragma unroll
        for (int k = 0; k < BK; k++) {
            float4 a0 = *reinterpret_cast<const float4*>(&As[buf][k][ty]);
            float4 a1 = *reinterpret_cast<const float4*>(&As[buf][k][ty + 64]);
            ulonglong2 b0 = *reinterpret_cast<const ulonglong2*>(&Bs[buf][k][tx]);
            ulonglong2 b1 = *reinterpret_cast<const ulonglong2*>(&Bs[buf][k][tx + 64]);
            ull ap[8];
            ap[0] = bcast2(a0.x); ap[1] = bcast2(a0.y);
            ap[2] = bcast2(a0.z); ap[3] = bcast2(a0.w);
            ap[4] = bcast2(a1.x); ap[5] = bcast2(a1.y);
            ap[6] = bcast2(a1.z); ap[7] = bcast2(a1.w);
            ull bb[4] = {b0.x, b0.y, b1.x, b1.y};
            #pragma unroll
            for (int i = 0; i < 8; i++)
                #pragma unroll
                for (int j = 0; j < 4; j++)
                    ffma2(acc[i][j], ap[i], bb[j]);
        }

        // commit prefetched tile to the other buffer
        if (iter + 1 < NIT) {
            const int nb = buf ^ 1;
            As[nb][lc + 0][lr] = stA0.x; As[nb][lc + 1][lr] = stA0.y;
            As[nb][lc + 2][lr] = stA0.z; As[nb][lc + 3][lr] = stA0.w;
            As[nb][lc + 0][lr + 64] = stA1.x; As[nb][lc + 1][lr + 64] = stA1.y;
            As[nb][lc + 2][lr + 64] = stA1.z; As[nb][lc + 3][lr + 64] = stA1.w;
            Bs[nb][lc + 0][lr] = stB0.x; Bs[nb][lc + 1][lr] = stB0.y;
            Bs[nb][lc + 2][lr] = stB0.z; Bs[nb][lc + 3][lr] = stB0.w;
            Bs[nb][lc + 0][lr + 64] = stB1.x; Bs[nb][lc + 1][lr + 64] = stB1.y;
            Bs[nb][lc + 2][lr + 64] = stB1.z; Bs[nb][lc + 3][lr + 64] = stB1.w;
            __syncthreads();
            buf = nb;
        }

        // panel boundary: fold chain into cross-panel sum (ONE rounded add/lane)
        if (((iter + 1) * BK) % KC == 0) {
            #pragma unroll
            for (int i = 0; i < 8; i++)
                #pragma unroll
                for (int j = 0; j < 4; j++) {
                    fadd2(sum[i][j], acc[i][j]);
                    acc[i][j] = 0ull;
                }
        }
    }

    // epilogue: ONE rounded bias add per lane, then 16B stores
    const ull* bq0 = reinterpret_cast<const ull*>(&bias[bn + tx]);
    const ull* bq1 = reinterpret_cast<const ull*>(&bias[bn + tx + 64]);
    ull bv[4] = {bq0[0], bq0[1], bq1[0], bq1[1]};

    #pragma unroll
    for (int i = 0; i < 8; i++) {
        int row = bm + ((i < 4) ? (ty + i) : (ty + 64 + (i - 4)));
        ull v0 = sum[i][0], v1 = sum[i][1], v2 = sum[i][2], v3 = sum[i][3];
        fadd2(v0, bv[0]); fadd2(v1, bv[1]); fadd2(v2, bv[2]); fadd2(v3, bv[3]);
        ulonglong2 o0; o0.x = v0; o0.y = v1;
        ulonglong2 o1; o1.x = v2; o1.y = v3;
        *reinterpret_cast<ulonglong2*>(&C[(size_t)row * N + bn + tx]) = o0;
        *reinterpret_cast<ulonglong2*>(&C[(size_t)row * N + bn + tx + 64]) = o1;
    }
}

// ---------------------------------------------------------------------------
// LIF recurrence, 4 neurons per thread (float4), XLA-exact op ordering per
// lane (no FMA contraction). Independent lanes -> bit-exact vs scalar.
// ---------------------------------------------------------------------------
__device__ __forceinline__ void lif_step(float& mem, float& s, float c, float thr) {
    float t0 = __fmul_rn(BETA_F, mem);
    float t1 = __fadd_rn(t0, c);
    float t2 = __fmul_rn(s, thr);
    mem = __fsub_rn(t1, t2);
    s = (__fsub_rn(mem, thr) > 0.f) ? 1.0f : 0.0f;
}

__global__ void lif_scan4(const float4* __restrict__ cur,
                          const float* __restrict__ thr_p,
                          float4* __restrict__ spk_rec,
                          int stride4 /* (BATCH*N)/4 per timestep */)
{
    const int idx = blockIdx.x * blockDim.x + threadIdx.x;
    const float thr = *thr_p;
    float4 mem = {0.f, 0.f, 0.f, 0.f};
    float4 s   = {0.f, 0.f, 0.f, 0.f};
    const float4* p = cur + idx;
    float4* q = spk_rec + idx;
    #pragma unroll 8
    for (int t = 0; t < T_STEPS; t++) {
        float4 c = p[(size_t)t * stride4];
        lif_step(mem.x, s.x, c.x, thr);
        lif_step(mem.y, s.y, c.y, thr);
        lif_step(mem.z, s.z, c.z, thr);
        lif_step(mem.w, s.w, c.w, thr);
        q[(size_t)t * stride4] = s;
    }
}

// ---------------------------------------------------------------------------
extern "C" void kernel_launch(void* const* d_in, const int* in_sizes, int n_in,
                              void* d_out, int out_size)
{
    const float* x    = (const float*)d_in[0];  // [T,B,I]
    const float* w1   = (const float*)d_in[1];  // [H,I]
    const float* b1   = (const float*)d_in[2];  // [H]
    const float* w2   = (const float*)d_in[3];  // [O,H]
    const float* b2   = (const float*)d_in[4];  // [O]
    const float* thr1 = (const float*)d_in[5];  // scalar
    const float* thr2 = (const float*)d_in[6];  // scalar

    float* out  = (float*)d_out;
    float* spk1 = out;                                    // [T,B,H]
    float* spk2 = out + (size_t)T_STEPS * BATCH * HID;    // [T,B,O]

    float* cur1 = nullptr;
    float* cur2 = nullptr;
    cudaGetSymbolAddress((void**)&cur1, g_cur1);
    cudaGetSymbolAddress((void**)&cur2, g_cur2);

    // 1) cur1 = X @ W1^T + b1   (32768 x 1024, K=1024)
    {
        dim3 grid(HID / BN, MROWS / BM);
        sgemm_nt_x2<<<grid, 256>>>(x, w1, b1, cur1, MROWS, HID, INDIM);
    }
    // 2) LIF layer 1 -> spk1_rec  (131072 neurons / 4 per thread)
    lif_scan4<<<(BATCH * HID / 4) / 256, 256>>>(
        (const float4*)cur1, thr1, (float4*)spk1, (BATCH * HID) / 4);

    // 3) cur2 = spk1_rec @ W2^T + b2   (32768 x 256, K=1024)
    {
        dim3 grid(OUTDIM / BN, MROWS / BM);
        sgemm_nt_x2<<<grid, 256>>>(spk1, w2, b2, cur2, MROWS, OUTDIM, HID);
    }
    // 4) LIF layer 2 -> spk2_rec  (32768 neurons / 4 per thread)
    lif_scan4<<<(BATCH * OUTDIM / 4) / 128, 128>>>(
        (const float4*)cur2, thr2, (float4*)spk2, (BATCH * OUTDIM) / 4);
}

// round 6
// speedup vs baseline: 1.0604x; 1.0338x over previous
#include <cuda_runtime.h>
#include <cstdint>

// Problem dims
#define T_STEPS 256
#define BATCH   128
#define INDIM   1024
#define HID     1024
#define OUTDIM  256
#define MROWS   (T_STEPS * BATCH)   // 32768
#define BETA_F  0.9f
#define KC      512                 // Eigen gebp panel depth (bit-exactness contract)

// Scratch (allocation-free rule: __device__ globals)
__device__ float g_cur1[(size_t)MROWS * HID];    // 128 MB
__device__ float g_cur2[(size_t)MROWS * OUTDIM]; // 32 MB

typedef unsigned long long ull;

// ---- packed f32x2 helpers (each lane = independent IEEE fp32 rn op) --------
__device__ __forceinline__ void ffma2(ull& d, ull a, ull b) {
    asm("fma.rn.f32x2 %0, %1, %2, %0;" : "+l"(d) : "l"(a), "l"(b));
}
__device__ __forceinline__ void fadd2(ull& d, ull a) {
    asm("add.rn.f32x2 %0, %0, %1;" : "+l"(d) : "l"(a));
}
__device__ __forceinline__ ull bcast2(float x) {
    ull r; asm("mov.b64 %0, {%1, %1};" : "=l"(r) : "f"(x)); return r;
}
__device__ __forceinline__ void unpack2(float& lo, float& hi, ull v) {
    asm("mov.b64 {%0, %1}, %2;" : "=f"(lo), "=f"(hi) : "l"(v));
}

// ---- no-op kernel: shifts app launch indices so ncu -s 5 captures GEMM1 ----
__global__ void noop_kernel() {}

// ---------------------------------------------------------------------------
// SGEMM NT: C[M,N] = A[M,K] * B[N,K]^T + bias[N], FFMA2 with M-paired lanes.
// Numerics contract (bit-match Eigen gebp kc=512, VERIFIED rel_err==0):
//   per element: S = fadd( chain(k=0..511), chain(k=512..1023) ), chains are
//   ascending-k fp32 FMA chains from 0; then ONE rounded bias add.
// Pairing over M: A operand pairs come straight out of LDS.128 as aligned
// 64-bit halves (no pack MOVs); only the B operand needs a broadcast MOV.
// Tile 128x128x16, 256 threads, microtile 8m(4 pairs) x 8n.
// Double-buffered smem, register-staged global prefetch, 1 sync/iter.
// ---------------------------------------------------------------------------
#define BM 128
#define BN 128
#define BK 16

__global__ __launch_bounds__(256, 1)
void sgemm_nt_x2(const float* __restrict__ A,
                 const float* __restrict__ B,
                 const float* __restrict__ bias,
                 float* __restrict__ C,
                 int M, int N, int K)
{
    __shared__ __align__(16) float As[2][BK][BM];
    __shared__ __align__(16) float Bs[2][BK][BN];

    const int tid = threadIdx.x;
    const int bm = blockIdx.y * BM;
    const int bn = blockIdx.x * BN;

    // global-load indexing: each thread stages 2 float4 from A and 2 from B
    const int lr = tid >> 2;          // 0..63
    const int lc = (tid & 3) << 2;    // 0,4,8,12

    // compute indexing: quadrant layout (16B-contiguous across 16 threads)
    const int tx = (tid & 15) << 2;   // n base (4 wide); second group at +64
    const int ty = (tid >> 4) << 2;   // m base (4 tall); second group at +64

    ull acc[4][8];   // within-panel chains: 4 m-pairs x 8 n
    ull sum[4][8];   // cross-panel accumulator
    #pragma unroll
    for (int i = 0; i < 4; i++)
        #pragma unroll
        for (int j = 0; j < 8; j++) { acc[i][j] = 0ull; sum[i][j] = 0ull; }

    // ---- prologue: stage tile 0, commit to buffer 0 ----
    float4 stA0 = *reinterpret_cast<const float4*>(&A[(size_t)(bm + lr) * K + lc]);
    float4 stA1 = *reinterpret_cast<const float4*>(&A[(size_t)(bm + lr + 64) * K + lc]);
    float4 stB0 = *reinterpret_cast<const float4*>(&B[(size_t)(bn + lr) * K + lc]);
    float4 stB1 = *reinterpret_cast<const float4*>(&B[(size_t)(bn + lr + 64) * K + lc]);

    As[0][lc + 0][lr] = stA0.x; As[0][lc + 1][lr] = stA0.y;
    As[0][lc + 2][lr] = stA0.z; As[0][lc + 3][lr] = stA0.w;
    As[0][lc + 0][lr + 64] = stA1.x; As[0][lc + 1][lr + 64] = stA1.y;
    As[0][lc + 2][lr + 64] = stA1.z; As[0][lc + 3][lr + 64] = stA1.w;
    Bs[0][lc + 0][lr] = stB0.x; Bs[0][lc + 1][lr] = stB0.y;
    Bs[0][lc + 2][lr] = stB0.z; Bs[0][lc + 3][lr] = stB0.w;
    Bs[0][lc + 0][lr + 64] = stB1.x; Bs[0][lc + 1][lr + 64] = stB1.y;
    Bs[0][lc + 2][lr + 64] = stB1.z; Bs[0][lc + 3][lr + 64] = stB1.w;
    __syncthreads();

    const int NIT = K / BK;  // 64
    int buf = 0;

    for (int iter = 0; iter < NIT; iter++) {
        // prefetch next tile into registers (latency hidden by compute)
        if (iter + 1 < NIT) {
            const int kn = (iter + 1) * BK + lc;
            stA0 = *reinterpret_cast<const float4*>(&A[(size_t)(bm + lr) * K + kn]);
            stA1 = *reinterpret_cast<const float4*>(&A[(size_t)(bm + lr + 64) * K + kn]);
            stB0 = *reinterpret_cast<const float4*>(&B[(size_t)(bn + lr) * K + kn]);
            stB1 = *reinterpret_cast<const float4*>(&B[(size_t)(bn + lr + 64) * K + kn]);
        }

        // compute: ascending-k FFMA2 chains, lanes paired over M
        #pragma unroll
        for (int k = 0; k < BK; k++) {
            // A pairs: direct 64-bit halves of LDS.128 (aligned, no MOVs)
            ulonglong2 av0 = *reinterpret_cast<const ulonglong2*>(&As[buf][k][ty]);
            ulonglong2 av1 = *reinterpret_cast<const ulonglong2*>(&As[buf][k][ty + 64]);
            float4 b0 = *reinterpret_cast<const float4*>(&Bs[buf][k][tx]);
            float4 b1 = *reinterpret_cast<const float4*>(&Bs[buf][k][tx + 64]);
            ull ap[4] = {av0.x, av0.y, av1.x, av1.y};
            ull bb[8];
            bb[0] = bcast2(b0.x); bb[1] = bcast2(b0.y);
            bb[2] = bcast2(b0.z); bb[3] = bcast2(b0.w);
            bb[4] = bcast2(b1.x); bb[5] = bcast2(b1.y);
            bb[6] = bcast2(b1.z); bb[7] = bcast2(b1.w);
            #pragma unroll
            for (int i = 0; i < 4; i++)
                #pragma unroll
                for (int j = 0; j < 8; j++)
                    ffma2(acc[i][j], ap[i], bb[j]);
        }

        // commit prefetched tile to the other buffer
        if (iter + 1 < NIT) {
            const int nb = buf ^ 1;
            As[nb][lc + 0][lr] = stA0.x; As[nb][lc + 1][lr] = stA0.y;
            As[nb][lc + 2][lr] = stA0.z; As[nb][lc + 3][lr] = stA0.w;
            As[nb][lc + 0][lr + 64] = stA1.x; As[nb][lc + 1][lr + 64] = stA1.y;
            As[nb][lc + 2][lr + 64] = stA1.z; As[nb][lc + 3][lr + 64] = stA1.w;
            Bs[nb][lc + 0][lr] = stB0.x; Bs[nb][lc + 1][lr] = stB0.y;
            Bs[nb][lc + 2][lr] = stB0.z; Bs[nb][lc + 3][lr] = stB0.w;
            Bs[nb][lc + 0][lr + 64] = stB1.x; Bs[nb][lc + 1][lr + 64] = stB1.y;
            Bs[nb][lc + 2][lr + 64] = stB1.z; Bs[nb][lc + 3][lr + 64] = stB1.w;
            __syncthreads();
            buf = nb;
        }

        // panel boundary: fold chain into cross-panel sum (ONE rounded add/lane)
        if (((iter + 1) * BK) % KC == 0) {
            #pragma unroll
            for (int i = 0; i < 4; i++)
                #pragma unroll
                for (int j = 0; j < 8; j++) {
                    fadd2(sum[i][j], acc[i][j]);
                    acc[i][j] = 0ull;
                }
        }
    }

    // epilogue: unpack M-pairs, ONE rounded bias add per element, 16B stores
    float4 bv0 = *reinterpret_cast<const float4*>(&bias[bn + tx]);
    float4 bv1 = *reinterpret_cast<const float4*>(&bias[bn + tx + 64]);
    const float bb[8] = {bv0.x, bv0.y, bv0.z, bv0.w, bv1.x, bv1.y, bv1.z, bv1.w};

    #pragma unroll
    for (int i = 0; i < 4; i++) {
        int r0 = bm + ((i < 2) ? (ty + 2 * i) : (ty + 64 + 2 * (i - 2)));
        float lo[8], hi[8];
        #pragma unroll
        for (int j = 0; j < 8; j++) {
            unpack2(lo[j], hi[j], sum[i][j]);
            lo[j] = __fadd_rn(lo[j], bb[j]);
            hi[j] = __fadd_rn(hi[j], bb[j]);
        }
        float4 s0 = {lo[0], lo[1], lo[2], lo[3]};
        float4 s1 = {lo[4], lo[5], lo[6], lo[7]};
        float4 s2 = {hi[0], hi[1], hi[2], hi[3]};
        float4 s3 = {hi[4], hi[5], hi[6], hi[7]};
        *reinterpret_cast<float4*>(&C[(size_t)r0 * N + bn + tx]) = s0;
        *reinterpret_cast<float4*>(&C[(size_t)r0 * N + bn + tx + 64]) = s1;
        *reinterpret_cast<float4*>(&C[(size_t)(r0 + 1) * N + bn + tx]) = s2;
        *reinterpret_cast<float4*>(&C[(size_t)(r0 + 1) * N + bn + tx + 64]) = s3;
    }
}

// ---------------------------------------------------------------------------
// LIF recurrence, XLA-exact op ordering per lane (no FMA contraction).
// Loads across t are independent (cur precomputed) -> prefetch next t to
// raise MLP above 1 on the latency-bound serial scan.
// ---------------------------------------------------------------------------
__device__ __forceinline__ void lif_step(float& mem, float& s, float c, float thr) {
    float t0 = __fmul_rn(BETA_F, mem);
    float t1 = __fadd_rn(t0, c);
    float t2 = __fmul_rn(s, thr);
    mem = __fsub_rn(t1, t2);
    s = (__fsub_rn(mem, thr) > 0.f) ? 1.0f : 0.0f;
}

__global__ void lif_scan4(const float4* __restrict__ cur,
                          const float* __restrict__ thr_p,
                          float4* __restrict__ spk_rec,
                          int stride4)
{
    const int idx = blockIdx.x * blockDim.x + threadIdx.x;
    const float thr = *thr_p;
    float4 mem = {0.f, 0.f, 0.f, 0.f};
    float4 s   = {0.f, 0.f, 0.f, 0.f};
    const float4* p = cur + idx;
    float4* q = spk_rec + idx;
    float4 c = p[0];
    #pragma unroll 4
    for (int t = 0; t < T_STEPS; t++) {
        float4 cn = {0.f, 0.f, 0.f, 0.f};
        if (t + 1 < T_STEPS) cn = p[(size_t)(t + 1) * stride4];
        lif_step(mem.x, s.x, c.x, thr);
        lif_step(mem.y, s.y, c.y, thr);
        lif_step(mem.z, s.z, c.z, thr);
        lif_step(mem.w, s.w, c.w, thr);
        q[(size_t)t * stride4] = s;
        c = cn;
    }
}

__global__ void lif_scan1(const float* __restrict__ cur,
                          const float* __restrict__ thr_p,
                          float* __restrict__ spk_rec,
                          int stride)
{
    const int idx = blockIdx.x * blockDim.x + threadIdx.x;
    const float thr = *thr_p;
    float mem = 0.f, s = 0.f;
    const float* p = cur + idx;
    float* q = spk_rec + idx;
    float c = p[0];
    #pragma unroll 8
    for (int t = 0; t < T_STEPS; t++) {
        float cn = 0.f;
        if (t + 1 < T_STEPS) cn = p[(size_t)(t + 1) * stride];
        lif_step(mem, s, c, thr);
        q[(size_t)t * stride] = s;
        c = cn;
    }
}

// ---------------------------------------------------------------------------
extern "C" void kernel_launch(void* const* d_in, const int* in_sizes, int n_in,
                              void* d_out, int out_size)
{
    const float* x    = (const float*)d_in[0];  // [T,B,I]
    const float* w1   = (const float*)d_in[1];  // [H,I]
    const float* b1   = (const float*)d_in[2];  // [H]
    const float* w2   = (const float*)d_in[3];  // [O,H]
    const float* b2   = (const float*)d_in[4];  // [O]
    const float* thr1 = (const float*)d_in[5];  // scalar
    const float* thr2 = (const float*)d_in[6];  // scalar

    float* out  = (float*)d_out;
    float* spk1 = out;                                    // [T,B,H]
    float* spk2 = out + (size_t)T_STEPS * BATCH * HID;    // [T,B,O]

    float* cur1 = nullptr;
    float* cur2 = nullptr;
    cudaGetSymbolAddress((void**)&cur1, g_cur1);
    cudaGetSymbolAddress((void**)&cur2, g_cur2);

    // 3 no-op launches: places GEMM1 at ncu's -s 5 capture slot (profiling aid)
    noop_kernel<<<1, 1>>>();
    noop_kernel<<<1, 1>>>();
    noop_kernel<<<1, 1>>>();

    // 1) cur1 = X @ W1^T + b1   (32768 x 1024, K=1024)
    {
        dim3 grid(HID / BN, MROWS / BM);
        sgemm_nt_x2<<<grid, 256>>>(x, w1, b1, cur1, MROWS, HID, INDIM);
    }
    // 2) LIF layer 1 -> spk1_rec  (131072 neurons / 4 per thread)
    lif_scan4<<<(BATCH * HID / 4) / 256, 256>>>(
        (const float4*)cur1, thr1, (float4*)spk1, (BATCH * HID) / 4);

    // 3) cur2 = spk1_rec @ W2^T + b2   (32768 x 256, K=1024)
    {
        dim3 grid(OUTDIM / BN, MROWS / BM);
        sgemm_nt_x2<<<grid, 256>>>(spk1, w2, b2, cur2, MROWS, OUTDIM, HID);
    }
    // 4) LIF layer 2 -> spk2_rec  (scalar: full thread count + prefetch)
    lif_scan1<<<(BATCH * OUTDIM) / 256, 256>>>(cur2, thr2, spk2, BATCH * OUTDIM);
}

// round 7
// speedup vs baseline: 1.4024x; 1.3225x over previous
#include <cuda_runtime.h>
#include <cstdint>

// Problem dims
#define T_STEPS 256
#define BATCH   128
#define INDIM   1024
#define HID     1024
#define OUTDIM  256
#define MROWS   (T_STEPS * BATCH)   // 32768
#define BETA_F  0.9f
#define KC      512                 // Eigen gebp panel depth (bit-exactness contract)

// Scratch (allocation-free rule: __device__ globals)
__device__ float g_cur1[(size_t)MROWS * HID];    // 128 MB
__device__ float g_cur2[(size_t)MROWS * OUTDIM]; // 32 MB

typedef unsigned long long ull;

// ---- packed f32x2 helpers (each lane = independent IEEE fp32 rn op) --------
__device__ __forceinline__ void ffma2(ull& d, ull a, ull b) {
    asm("fma.rn.f32x2 %0, %1, %2, %0;" : "+l"(d) : "l"(a), "l"(b));
}
__device__ __forceinline__ ull bcast2(float x) {
    ull r; asm("mov.b64 %0, {%1, %1};" : "=l"(r) : "f"(x)); return r;
}
__device__ __forceinline__ void unpack2(float& lo, float& hi, ull v) {
    asm("mov.b64 {%0, %1}, %2;" : "=f"(lo), "=f"(hi) : "l"(v));
}

// ---- no-op kernel: shifts app launch indices for ncu -s 5 capture ----------
__global__ void noop_kernel() {}

// ---------------------------------------------------------------------------
// SGEMM NT, ONE kc-panel per launch (phase): C = chain(A[k0..k0+511] * B^T)
//   phase 0: C = acc                      (raw panel-1 partial, exact bits)
//   phase 1: C = fadd( fadd(Cin, acc), bias )
// Per-element op sequence across the two launches == verified Eigen gebp
// kc=512 contract (rel_err == 0.0 in R4-R6).
// Dropping the cross-panel `sum` register file (-64 regs) enables
// 2 CTAs/SM -> 4 warps/SMSP for latency hiding.
// Tile 128x128x16, 256 threads, microtile 8m(4 f32x2 pairs) x 8n.
// ---------------------------------------------------------------------------
#define BM 128
#define BN 128
#define BK 16

__global__ __launch_bounds__(256, 2)
void sgemm_panel(const float* __restrict__ A,   // already offset to k0
                 const float* __restrict__ B,   // already offset to k0
                 const float* __restrict__ bias,
                 float* __restrict__ C,
                 int N, int K /* full K for row stride */,
                 int addBias /* 0: phase0, 1: phase1 */)
{
    __shared__ __align__(16) float As[2][BK][BM];
    __shared__ __align__(16) float Bs[2][BK][BN];

    const int tid = threadIdx.x;
    const int bm = blockIdx.y * BM;
    const int bn = blockIdx.x * BN;

    // global-load indexing: each thread stages 2 float4 from A and 2 from B
    const int lr = tid >> 2;          // 0..63
    const int lc = (tid & 3) << 2;    // 0,4,8,12

    // compute indexing: quadrant layout
    const int tx = (tid & 15) << 2;   // n base (4 wide); second group at +64
    const int ty = (tid >> 4) << 2;   // m base (4 tall); second group at +64

    ull acc[4][8];   // panel chains: 4 m-pairs x 8 n
    #pragma unroll
    for (int i = 0; i < 4; i++)
        #pragma unroll
        for (int j = 0; j < 8; j++) acc[i][j] = 0ull;

    // ---- prologue: stage tile 0, commit to buffer 0 ----
    float4 stA0 = *reinterpret_cast<const float4*>(&A[(size_t)(bm + lr) * K + lc]);
    float4 stA1 = *reinterpret_cast<const float4*>(&A[(size_t)(bm + lr + 64) * K + lc]);
    float4 stB0 = *reinterpret_cast<const float4*>(&B[(size_t)(bn + lr) * K + lc]);
    float4 stB1 = *reinterpret_cast<const float4*>(&B[(size_t)(bn + lr + 64) * K + lc]);

    As[0][lc + 0][lr] = stA0.x; As[0][lc + 1][lr] = stA0.y;
    As[0][lc + 2][lr] = stA0.z; As[0][lc + 3][lr] = stA0.w;
    As[0][lc + 0][lr + 64] = stA1.x; As[0][lc + 1][lr + 64] = stA1.y;
    As[0][lc + 2][lr + 64] = stA1.z; As[0][lc + 3][lr + 64] = stA1.w;
    Bs[0][lc + 0][lr] = stB0.x; Bs[0][lc + 1][lr] = stB0.y;
    Bs[0][lc + 2][lr] = stB0.z; Bs[0][lc + 3][lr] = stB0.w;
    Bs[0][lc + 0][lr + 64] = stB1.x; Bs[0][lc + 1][lr + 64] = stB1.y;
    Bs[0][lc + 2][lr + 64] = stB1.z; Bs[0][lc + 3][lr + 64] = stB1.w;
    __syncthreads();

    const int NIT = KC / BK;  // 32 iterations per panel
    int buf = 0;

    for (int iter = 0; iter < NIT; iter++) {
        // prefetch next tile into registers (latency hidden by compute)
        if (iter + 1 < NIT) {
            const int kn = (iter + 1) * BK + lc;
            stA0 = *reinterpret_cast<const float4*>(&A[(size_t)(bm + lr) * K + kn]);
            stA1 = *reinterpret_cast<const float4*>(&A[(size_t)(bm + lr + 64) * K + kn]);
            stB0 = *reinterpret_cast<const float4*>(&B[(size_t)(bn + lr) * K + kn]);
            stB1 = *reinterpret_cast<const float4*>(&B[(size_t)(bn + lr + 64) * K + kn]);
        }

        // compute: ascending-k FFMA2 chains, lanes paired over M
        #pragma unroll
        for (int k = 0; k < BK; k++) {
            ulonglong2 av0 = *reinterpret_cast<const ulonglong2*>(&As[buf][k][ty]);
            ulonglong2 av1 = *reinterpret_cast<const ulonglong2*>(&As[buf][k][ty + 64]);
            float4 b0 = *reinterpret_cast<const float4*>(&Bs[buf][k][tx]);
            float4 b1 = *reinterpret_cast<const float4*>(&Bs[buf][k][tx + 64]);
            ull ap[4] = {av0.x, av0.y, av1.x, av1.y};
            ull bb[8];
            bb[0] = bcast2(b0.x); bb[1] = bcast2(b0.y);
            bb[2] = bcast2(b0.z); bb[3] = bcast2(b0.w);
            bb[4] = bcast2(b1.x); bb[5] = bcast2(b1.y);
            bb[6] = bcast2(b1.z); bb[7] = bcast2(b1.w);
            #pragma unroll
            for (int i = 0; i < 4; i++)
                #pragma unroll
                for (int j = 0; j < 8; j++)
                    ffma2(acc[i][j], ap[i], bb[j]);
        }

        // commit prefetched tile to the other buffer
        if (iter + 1 < NIT) {
            const int nb = buf ^ 1;
            As[nb][lc + 0][lr] = stA0.x; As[nb][lc + 1][lr] = stA0.y;
            As[nb][lc + 2][lr] = stA0.z; As[nb][lc + 3][lr] = stA0.w;
            As[nb][lc + 0][lr + 64] = stA1.x; As[nb][lc + 1][lr + 64] = stA1.y;
            As[nb][lc + 2][lr + 64] = stA1.z; As[nb][lc + 3][lr + 64] = stA1.w;
            Bs[nb][lc + 0][lr] = stB0.x; Bs[nb][lc + 1][lr] = stB0.y;
            Bs[nb][lc + 2][lr] = stB0.z; Bs[nb][lc + 3][lr] = stB0.w;
            Bs[nb][lc + 0][lr + 64] = stB1.x; Bs[nb][lc + 1][lr + 64] = stB1.y;
            Bs[nb][lc + 2][lr + 64] = stB1.z; Bs[nb][lc + 3][lr + 64] = stB1.w;
            __syncthreads();
            buf = nb;
        }
    }

    // ---- epilogue ----
    if (addBias) {
        // phase 1: v = fadd( fadd(C_panel1, acc_panel2), bias ), per element
        float4 bv0 = *reinterpret_cast<const float4*>(&bias[bn + tx]);
        float4 bv1 = *reinterpret_cast<const float4*>(&bias[bn + tx + 64]);
        const float bb[8] = {bv0.x, bv0.y, bv0.z, bv0.w, bv1.x, bv1.y, bv1.z, bv1.w};
        #pragma unroll
        for (int i = 0; i < 4; i++) {
            int r0 = bm + ((i < 2) ? (ty + 2 * i) : (ty + 64 + 2 * (i - 2)));
            #pragma unroll
            for (int half = 0; half < 2; half++) {
                int row = r0 + half;
                float4 p0 = *reinterpret_cast<const float4*>(&C[(size_t)row * N + bn + tx]);
                float4 p1 = *reinterpret_cast<const float4*>(&C[(size_t)row * N + bn + tx + 64]);
                float pr[8] = {p0.x, p0.y, p0.z, p0.w, p1.x, p1.y, p1.z, p1.w};
                float o[8];
                #pragma unroll
                for (int j = 0; j < 8; j++) {
                    float lo, hi;
                    unpack2(lo, hi, acc[i][j]);
                    float mine = half ? hi : lo;
                    o[j] = __fadd_rn(__fadd_rn(pr[j], mine), bb[j]);
                }
                float4 s0 = {o[0], o[1], o[2], o[3]};
                float4 s1 = {o[4], o[5], o[6], o[7]};
                *reinterpret_cast<float4*>(&C[(size_t)row * N + bn + tx]) = s0;
                *reinterpret_cast<float4*>(&C[(size_t)row * N + bn + tx + 64]) = s1;
            }
        }
    } else {
        // phase 0: store raw panel-1 partials (exact bits)
        #pragma unroll
        for (int i = 0; i < 4; i++) {
            int r0 = bm + ((i < 2) ? (ty + 2 * i) : (ty + 64 + 2 * (i - 2)));
            float lo[8], hi[8];
            #pragma unroll
            for (int j = 0; j < 8; j++) unpack2(lo[j], hi[j], acc[i][j]);
            float4 s0 = {lo[0], lo[1], lo[2], lo[3]};
            float4 s1 = {lo[4], lo[5], lo[6], lo[7]};
            float4 s2 = {hi[0], hi[1], hi[2], hi[3]};
            float4 s3 = {hi[4], hi[5], hi[6], hi[7]};
            *reinterpret_cast<float4*>(&C[(size_t)r0 * N + bn + tx]) = s0;
            *reinterpret_cast<float4*>(&C[(size_t)r0 * N + bn + tx + 64]) = s1;
            *reinterpret_cast<float4*>(&C[(size_t)(r0 + 1) * N + bn + tx]) = s2;
            *reinterpret_cast<float4*>(&C[(size_t)(r0 + 1) * N + bn + tx + 64]) = s3;
        }
    }
}

// ---------------------------------------------------------------------------
// LIF recurrence, XLA-exact op ordering per lane (no FMA contraction).
// ---------------------------------------------------------------------------
__device__ __forceinline__ void lif_step(float& mem, float& s, float c, float thr) {
    float t0 = __fmul_rn(BETA_F, mem);
    float t1 = __fadd_rn(t0, c);
    float t2 = __fmul_rn(s, thr);
    mem = __fsub_rn(t1, t2);
    s = (__fsub_rn(mem, thr) > 0.f) ? 1.0f : 0.0f;
}

__global__ void lif_scan4(const float4* __restrict__ cur,
                          const float* __restrict__ thr_p,
                          float4* __restrict__ spk_rec,
                          int stride4)
{
    const int idx = blockIdx.x * blockDim.x + threadIdx.x;
    const float thr = *thr_p;
    float4 mem = {0.f, 0.f, 0.f, 0.f};
    float4 s   = {0.f, 0.f, 0.f, 0.f};
    const float4* p = cur + idx;
    float4* q = spk_rec + idx;
    float4 c = p[0];
    #pragma unroll 4
    for (int t = 0; t < T_STEPS; t++) {
        float4 cn = {0.f, 0.f, 0.f, 0.f};
        if (t + 1 < T_STEPS) cn = p[(size_t)(t + 1) * stride4];
        lif_step(mem.x, s.x, c.x, thr);
        lif_step(mem.y, s.y, c.y, thr);
        lif_step(mem.z, s.z, c.z, thr);
        lif_step(mem.w, s.w, c.w, thr);
        q[(size_t)t * stride4] = s;
        c = cn;
    }
}

__global__ void lif_scan1(const float* __restrict__ cur,
                          const float* __restrict__ thr_p,
                          float* __restrict__ spk_rec,
                          int stride)
{
    const int idx = blockIdx.x * blockDim.x + threadIdx.x;
    const float thr = *thr_p;
    float mem = 0.f, s = 0.f;
    const float* p = cur + idx;
    float* q = spk_rec + idx;
    float c = p[0];
    #pragma unroll 8
    for (int t = 0; t < T_STEPS; t++) {
        float cn = 0.f;
        if (t + 1 < T_STEPS) cn = p[(size_t)(t + 1) * stride];
        lif_step(mem, s, c, thr);
        q[(size_t)t * stride] = s;
        c = cn;
    }
}

// ---------------------------------------------------------------------------
extern "C" void kernel_launch(void* const* d_in, const int* in_sizes, int n_in,
                              void* d_out, int out_size)
{
    const float* x    = (const float*)d_in[0];  // [T,B,I]
    const float* w1   = (const float*)d_in[1];  // [H,I]
    const float* b1   = (const float*)d_in[2];  // [H]
    const float* w2   = (const float*)d_in[3];  // [O,H]
    const float* b2   = (const float*)d_in[4];  // [O]
    const float* thr1 = (const float*)d_in[5];  // scalar
    const float* thr2 = (const float*)d_in[6];  // scalar

    float* out  = (float*)d_out;
    float* spk1 = out;                                    // [T,B,H]
    float* spk2 = out + (size_t)T_STEPS * BATCH * HID;    // [T,B,O]

    float* cur1 = nullptr;
    float* cur2 = nullptr;
    cudaGetSymbolAddress((void**)&cur1, g_cur1);
    cudaGetSymbolAddress((void**)&cur2, g_cur2);

    // 3 no-op launches: keeps GEMM1 at ncu's capture slot (profiling aid)
    noop_kernel<<<1, 1>>>();
    noop_kernel<<<1, 1>>>();
    noop_kernel<<<1, 1>>>();

    // 1) cur1 = X @ W1^T + b1   (two kc=512 panel launches)
    {
        dim3 grid(HID / BN, MROWS / BM);
        sgemm_panel<<<grid, 256>>>(x, w1, b1, cur1, HID, INDIM, 0);
        sgemm_panel<<<grid, 256>>>(x + KC, w1 + KC, b1, cur1, HID, INDIM, 1);
    }
    // 2) LIF layer 1 -> spk1_rec
    lif_scan4<<<(BATCH * HID / 4) / 256, 256>>>(
        (const float4*)cur1, thr1, (float4*)spk1, (BATCH * HID) / 4);

    // 3) cur2 = spk1_rec @ W2^T + b2   (two kc=512 panel launches)
    {
        dim3 grid(OUTDIM / BN, MROWS / BM);
        sgemm_panel<<<grid, 256>>>(spk1, w2, b2, cur2, OUTDIM, HID, 0);
        sgemm_panel<<<grid, 256>>>(spk1 + KC, w2 + KC, b2, cur2, OUTDIM, HID, 1);
    }
    // 4) LIF layer 2 -> spk2_rec
    lif_scan1<<<(BATCH * OUTDIM) / 256, 256>>>(cur2, thr2, spk2, BATCH * OUTDIM);
}

// round 8
// speedup vs baseline: 1.4914x; 1.0635x over previous
#include <cuda_runtime.h>
#include <cstdint>

// Problem dims
#define T_STEPS 256
#define BATCH   128
#define INDIM   1024
#define HID     1024
#define OUTDIM  256
#define MROWS   (T_STEPS * BATCH)   // 32768
#define BETA_F  0.9f
#define KC      512                 // Eigen gebp panel depth (bit-exactness contract)

// Scratch (allocation-free rule: __device__ globals)
__device__ float g_cur1[(size_t)MROWS * HID];     // 128 MB
__device__ float g_cur2[(size_t)MROWS * OUTDIM];  // 32 MB
__device__ float g_xT  [(size_t)INDIM * MROWS];   // 128 MB  x transposed (k-major)
__device__ float g_w1T [(size_t)INDIM * HID];     // 4 MB    w1 transposed
__device__ float g_w2T [(size_t)HID * OUTDIM];    // 1 MB    w2 transposed

typedef unsigned long long ull;

// ---- packed f32x2 helpers (each lane = independent IEEE fp32 rn op) --------
__device__ __forceinline__ void ffma2(ull& d, ull a, ull b) {
    asm("fma.rn.f32x2 %0, %1, %2, %0;" : "+l"(d) : "l"(a), "l"(b));
}
__device__ __forceinline__ ull bcast2(float x) {
    ull r; asm("mov.b64 %0, {%1, %1};" : "=l"(r) : "f"(x)); return r;
}
__device__ __forceinline__ void unpack2(float& lo, float& hi, ull v) {
    asm("mov.b64 {%0, %1}, %2;" : "=f"(lo), "=f"(hi) : "l"(v));
}

// ---- cp.async helpers ------------------------------------------------------
__device__ __forceinline__ void cp_async16(uint32_t smem, const void* g) {
    asm volatile("cp.async.cg.shared.global [%0], [%1], 16;" :: "r"(smem), "l"(g));
}
__device__ __forceinline__ void cp_commit() {
    asm volatile("cp.async.commit_group;" ::: "memory");
}
__device__ __forceinline__ void cp_wait0() {
    asm volatile("cp.async.wait_group 0;" ::: "memory");
}

// ---- no-op kernel: shifts app launch indices for ncu -s 5 capture ----------
__global__ void noop_kernel() {}

// ---------------------------------------------------------------------------
// Tiled transpose: in [rows][cols] -> out [cols][rows]. Pure bit copy.
// ---------------------------------------------------------------------------
__global__ void transpose32(const float* __restrict__ in, float* __restrict__ out,
                            int rows, int cols)
{
    __shared__ float tile[32][33];
    const int c0 = blockIdx.x * 32;
    const int r0 = blockIdx.y * 32;
    #pragma unroll
    for (int j = 0; j < 32; j += 8)
        tile[threadIdx.y + j][threadIdx.x] =
            in[(size_t)(r0 + threadIdx.y + j) * cols + c0 + threadIdx.x];
    __syncthreads();
    #pragma unroll
    for (int j = 0; j < 32; j += 8)
        out[(size_t)(c0 + threadIdx.y + j) * rows + r0 + threadIdx.x] =
            tile[threadIdx.x][threadIdx.y + j];
}

// ---------------------------------------------------------------------------
// SGEMM NT panel (kc=512), FFMA2, cp.async tile loads.
// Numerics contract (bit-match Eigen gebp kc=512, VERIFIED rel_err==0):
//   per element: S = fadd( chain(k=0..511), chain(k=512..1023) ), chains are
//   ascending-k fp32 FMA chains from 0; then ONE rounded bias add (phase 1).
// AMODE 0: A is k-major [K][M] (xT) -> cp.async, no staging regs.
// AMODE 1: A is m-major [M][K] (spk1) -> LDG + STS transpose (register staged).
// B always k-major [K][N] (wT) -> cp.async.
// Tile 128x128x16, 256 threads, microtile 8m(4 f32x2 m-pairs) x 8n.
// ---------------------------------------------------------------------------
#define BM 128
#define BN 128
#define BK 16
#define NITER (KC / BK)   // 32

template<int AMODE>
__global__ __launch_bounds__(256, 2)
void sgemm_panel(const float* __restrict__ A,
                 const float* __restrict__ B,
                 const float* __restrict__ bias,
                 float* __restrict__ C,
                 int lda, int ldb, int N, int addBias)
{
    __shared__ __align__(16) float As[2][BK][BM];
    __shared__ __align__(16) float Bs[2][BK][BN];

    const int tid = threadIdx.x;
    const int bm = blockIdx.y * BM;
    const int bn = blockIdx.x * BN;

    // compute indexing: quadrant layout
    const int tx = (tid & 15) << 2;   // n base (4 wide); second group at +64
    const int ty = (tid >> 4) << 2;   // m base (4 tall); second group at +64

    // cp.async chunk indexing: 16x128-float tile = 512 chunks of 16B;
    // thread t handles rows lk and lk+8 at column offset lof.
    const int lk  = tid >> 5;          // 0..7
    const int lof = (tid & 31) << 2;   // 0..124

    // AMODE 1 staging indexing (as R7)
    const int lr = tid >> 2;           // 0..63
    const int lc = (tid & 3) << 2;     // 0,4,8,12

    const uint32_t sA = (uint32_t)__cvta_generic_to_shared(&As[0][0][0]);
    const uint32_t sB = (uint32_t)__cvta_generic_to_shared(&Bs[0][0][0]);
    #define SA_ADDR(b, k, off) (sA + (uint32_t)(((b) * BK + (k)) * BM + (off)) * 4u)
    #define SB_ADDR(b, k, off) (sB + (uint32_t)(((b) * BK + (k)) * BN + (off)) * 4u)

    ull acc[4][8];   // panel chains: 4 m-pairs x 8 n
    #pragma unroll
    for (int i = 0; i < 4; i++)
        #pragma unroll
        for (int j = 0; j < 8; j++) acc[i][j] = 0ull;

    // ---- prologue: tile 0 into buffer 0 ----
    cp_async16(SB_ADDR(0, lk, lof),     &B[(size_t)lk * ldb + bn + lof]);
    cp_async16(SB_ADDR(0, lk + 8, lof), &B[(size_t)(lk + 8) * ldb + bn + lof]);
    if (AMODE == 0) {
        cp_async16(SA_ADDR(0, lk, lof),     &A[(size_t)lk * lda + bm + lof]);
        cp_async16(SA_ADDR(0, lk + 8, lof), &A[(size_t)(lk + 8) * lda + bm + lof]);
    } else {
        float4 a0 = *reinterpret_cast<const float4*>(&A[(size_t)(bm + lr) * lda + lc]);
        float4 a1 = *reinterpret_cast<const float4*>(&A[(size_t)(bm + lr + 64) * lda + lc]);
        As[0][lc + 0][lr] = a0.x; As[0][lc + 1][lr] = a0.y;
        As[0][lc + 2][lr] = a0.z; As[0][lc + 3][lr] = a0.w;
        As[0][lc + 0][lr + 64] = a1.x; As[0][lc + 1][lr + 64] = a1.y;
        As[0][lc + 2][lr + 64] = a1.z; As[0][lc + 3][lr + 64] = a1.w;
    }
    cp_commit();
    cp_wait0();
    __syncthreads();

    int buf = 0;
    for (int iter = 0; iter < NITER; iter++) {
        float4 stA0, stA1;
        if (iter + 1 < NITER) {
            const int kt = (iter + 1) * BK;
            const int nb = buf ^ 1;
            cp_async16(SB_ADDR(nb, lk, lof),     &B[(size_t)(kt + lk) * ldb + bn + lof]);
            cp_async16(SB_ADDR(nb, lk + 8, lof), &B[(size_t)(kt + lk + 8) * ldb + bn + lof]);
            if (AMODE == 0) {
                cp_async16(SA_ADDR(nb, lk, lof),     &A[(size_t)(kt + lk) * lda + bm + lof]);
                cp_async16(SA_ADDR(nb, lk + 8, lof), &A[(size_t)(kt + lk + 8) * lda + bm + lof]);
            } else {
                stA0 = *reinterpret_cast<const float4*>(&A[(size_t)(bm + lr) * lda + kt + lc]);
                stA1 = *reinterpret_cast<const float4*>(&A[(size_t)(bm + lr + 64) * lda + kt + lc]);
            }
            cp_commit();
        }

        // compute: ascending-k FFMA2 chains, lanes paired over M
        #pragma unroll
        for (int k = 0; k < BK; k++) {
            ulonglong2 av0 = *reinterpret_cast<const ulonglong2*>(&As[buf][k][ty]);
            ulonglong2 av1 = *reinterpret_cast<const ulonglong2*>(&As[buf][k][ty + 64]);
            float4 b0 = *reinterpret_cast<const float4*>(&Bs[buf][k][tx]);
            float4 b1 = *reinterpret_cast<const float4*>(&Bs[buf][k][tx + 64]);
            ull ap[4] = {av0.x, av0.y, av1.x, av1.y};
            ull bb[8];
            bb[0] = bcast2(b0.x); bb[1] = bcast2(b0.y);
            bb[2] = bcast2(b0.z); bb[3] = bcast2(b0.w);
            bb[4] = bcast2(b1.x); bb[5] = bcast2(b1.y);
            bb[6] = bcast2(b1.z); bb[7] = bcast2(b1.w);
            #pragma unroll
            for (int i = 0; i < 4; i++)
                #pragma unroll
                for (int j = 0; j < 8; j++)
                    ffma2(acc[i][j], ap[i], bb[j]);
        }

        if (iter + 1 < NITER) {
            const int nb = buf ^ 1;
            if (AMODE == 1) {
                As[nb][lc + 0][lr] = stA0.x; As[nb][lc + 1][lr] = stA0.y;
                As[nb][lc + 2][lr] = stA0.z; As[nb][lc + 3][lr] = stA0.w;
                As[nb][lc + 0][lr + 64] = stA1.x; As[nb][lc + 1][lr + 64] = stA1.y;
                As[nb][lc + 2][lr + 64] = stA1.z; As[nb][lc + 3][lr + 64] = stA1.w;
            }
            cp_wait0();
            __syncthreads();
            buf = nb;
        }
    }

    // ---- epilogue ----
    if (addBias) {
        // phase 1: v = fadd( fadd(C_panel1, acc_panel2), bias ), per element
        float4 bv0 = *reinterpret_cast<const float4*>(&bias[bn + tx]);
        float4 bv1 = *reinterpret_cast<const float4*>(&bias[bn + tx + 64]);
        const float bb[8] = {bv0.x, bv0.y, bv0.z, bv0.w, bv1.x, bv1.y, bv1.z, bv1.w};
        #pragma unroll
        for (int i = 0; i < 4; i++) {
            int r0 = bm + ((i < 2) ? (ty + 2 * i) : (ty + 64 + 2 * (i - 2)));
            #pragma unroll
            for (int half = 0; half < 2; half++) {
                int row = r0 + half;
                float4 p0 = *reinterpret_cast<const float4*>(&C[(size_t)row * N + bn + tx]);
                float4 p1 = *reinterpret_cast<const float4*>(&C[(size_t)row * N + bn + tx + 64]);
                float pr[8] = {p0.x, p0.y, p0.z, p0.w, p1.x, p1.y, p1.z, p1.w};
                float o[8];
                #pragma unroll
                for (int j = 0; j < 8; j++) {
                    float lo, hi;
                    unpack2(lo, hi, acc[i][j]);
                    float mine = half ? hi : lo;
                    o[j] = __fadd_rn(__fadd_rn(pr[j], mine), bb[j]);
                }
                float4 s0 = {o[0], o[1], o[2], o[3]};
                float4 s1 = {o[4], o[5], o[6], o[7]};
                *reinterpret_cast<float4*>(&C[(size_t)row * N + bn + tx]) = s0;
                *reinterpret_cast<float4*>(&C[(size_t)row * N + bn + tx + 64]) = s1;
            }
        }
    } else {
        // phase 0: store raw panel-1 partials (exact bits)
        #pragma unroll
        for (int i = 0; i < 4; i++) {
            int r0 = bm + ((i < 2) ? (ty + 2 * i) : (ty + 64 + 2 * (i - 2)));
            float lo[8], hi[8];
            #pragma unroll
            for (int j = 0; j < 8; j++) unpack2(lo[j], hi[j], acc[i][j]);
            float4 s0 = {lo[0], lo[1], lo[2], lo[3]};
            float4 s1 = {lo[4], lo[5], lo[6], lo[7]};
            float4 s2 = {hi[0], hi[1], hi[2], hi[3]};
            float4 s3 = {hi[4], hi[5], hi[6], hi[7]};
            *reinterpret_cast<float4*>(&C[(size_t)r0 * N + bn + tx]) = s0;
            *reinterpret_cast<float4*>(&C[(size_t)r0 * N + bn + tx + 64]) = s1;
            *reinterpret_cast<float4*>(&C[(size_t)(r0 + 1) * N + bn + tx]) = s2;
            *reinterpret_cast<float4*>(&C[(size_t)(r0 + 1) * N + bn + tx + 64]) = s3;
        }
    }
    #undef SA_ADDR
    #undef SB_ADDR
}

// ---------------------------------------------------------------------------
// LIF recurrence, XLA-exact op ordering per lane (no FMA contraction).
// ---------------------------------------------------------------------------
__device__ __forceinline__ void lif_step(float& mem, float& s, float c, float thr) {
    float t0 = __fmul_rn(BETA_F, mem);
    float t1 = __fadd_rn(t0, c);
    float t2 = __fmul_rn(s, thr);
    mem = __fsub_rn(t1, t2);
    s = (__fsub_rn(mem, thr) > 0.f) ? 1.0f : 0.0f;
}

__global__ void lif_scan4(const float4* __restrict__ cur,
                          const float* __restrict__ thr_p,
                          float4* __restrict__ spk_rec,
                          int stride4)
{
    const int idx = blockIdx.x * blockDim.x + threadIdx.x;
    const float thr = *thr_p;
    float4 mem = {0.f, 0.f, 0.f, 0.f};
    float4 s   = {0.f, 0.f, 0.f, 0.f};
    const float4* p = cur + idx;
    float4* q = spk_rec + idx;
    float4 c = p[0];
    #pragma unroll 4
    for (int t = 0; t < T_STEPS; t++) {
        float4 cn = {0.f, 0.f, 0.f, 0.f};
        if (t + 1 < T_STEPS) cn = p[(size_t)(t + 1) * stride4];
        lif_step(mem.x, s.x, c.x, thr);
        lif_step(mem.y, s.y, c.y, thr);
        lif_step(mem.z, s.z, c.z, thr);
        lif_step(mem.w, s.w, c.w, thr);
        q[(size_t)t * stride4] = s;
        c = cn;
    }
}

__global__ void lif_scan1(const float* __restrict__ cur,
                          const float* __restrict__ thr_p,
                          float* __restrict__ spk_rec,
                          int stride)
{
    const int idx = blockIdx.x * blockDim.x + threadIdx.x;
    const float thr = *thr_p;
    float mem = 0.f, s = 0.f;
    const float* p = cur + idx;
    float* q = spk_rec + idx;
    float c = p[0];
    #pragma unroll 8
    for (int t = 0; t < T_STEPS; t++) {
        float cn = 0.f;
        if (t + 1 < T_STEPS) cn = p[(size_t)(t + 1) * stride];
        lif_step(mem, s, c, thr);
        q[(size_t)t * stride] = s;
        c = cn;
    }
}

// ---------------------------------------------------------------------------
extern "C" void kernel_launch(void* const* d_in, const int* in_sizes, int n_in,
                              void* d_out, int out_size)
{
    const float* x    = (const float*)d_in[0];  // [T,B,I]
    const float* w1   = (const float*)d_in[1];  // [H,I]
    const float* b1   = (const float*)d_in[2];  // [H]
    const float* w2   = (const float*)d_in[3];  // [O,H]
    const float* b2   = (const float*)d_in[4];  // [O]
    const float* thr1 = (const float*)d_in[5];  // scalar
    const float* thr2 = (const float*)d_in[6];  // scalar

    float* out  = (float*)d_out;
    float* spk1 = out;                                    // [T,B,H]
    float* spk2 = out + (size_t)T_STEPS * BATCH * HID;    // [T,B,O]

    float *cur1, *cur2, *xT, *w1T, *w2T;
    cudaGetSymbolAddress((void**)&cur1, g_cur1);
    cudaGetSymbolAddress((void**)&cur2, g_cur2);
    cudaGetSymbolAddress((void**)&xT,  g_xT);
    cudaGetSymbolAddress((void**)&w1T, g_w1T);
    cudaGetSymbolAddress((void**)&w2T, g_w2T);

    // 2 no-ops: keeps GEMM1-phase0 at ncu's -s 5 capture slot (profiling aid)
    noop_kernel<<<1, 1>>>();
    noop_kernel<<<1, 1>>>();

    // prep: bit-copy transposes to k-major layouts
    transpose32<<<dim3(INDIM / 32, MROWS / 32), dim3(32, 8)>>>(x, xT, MROWS, INDIM);
    transpose32<<<dim3(INDIM / 32, HID / 32), dim3(32, 8)>>>(w1, w1T, HID, INDIM);
    transpose32<<<dim3(HID / 32, OUTDIM / 32), dim3(32, 8)>>>(w2, w2T, OUTDIM, HID);

    // 1) cur1 = X @ W1^T + b1   (two kc=512 panels; AMODE 0: both operands k-major)
    {
        dim3 grid(HID / BN, MROWS / BM);
        sgemm_panel<0><<<grid, 256>>>(xT, w1T, b1, cur1, MROWS, HID, HID, 0);
        sgemm_panel<0><<<grid, 256>>>(xT + (size_t)KC * MROWS, w1T + (size_t)KC * HID,
                                      b1, cur1, MROWS, HID, HID, 1);
    }
    // 2) LIF layer 1 -> spk1_rec
    lif_scan4<<<(BATCH * HID / 4) / 256, 256>>>(
        (const float4*)cur1, thr1, (float4*)spk1, (BATCH * HID) / 4);

    // 3) cur2 = spk1_rec @ W2^T + b2   (AMODE 1: A m-major, B k-major)
    {
        dim3 grid(OUTDIM / BN, MROWS / BM);
        sgemm_panel<1><<<grid, 256>>>(spk1, w2T, b2, cur2, HID, OUTDIM, OUTDIM, 0);
        sgemm_panel<1><<<grid, 256>>>(spk1 + KC, w2T + (size_t)KC * OUTDIM,
                                      b2, cur2, HID, OUTDIM, OUTDIM, 1);
    }
    // 4) LIF layer 2 -> spk2_rec
    lif_scan1<<<(BATCH * OUTDIM) / 256, 256>>>(cur2, thr2, spk2, BATCH * OUTDIM);
}